// round 15
// baseline (speedup 1.0000x reference)
#include <cuda_runtime.h>
#include <cuda_fp16.h>
#include <math.h>
#include <stdint.h>

#define H   16
#define DM  1024
#define DK  64
#define DV  64
#define SQ  2048
#define BB  2
#define NR  (SQ*BB)                 /* 4096 rows */
#define AELEMS ((size_t)NR*DM)      /* 4M elements per activation tensor */
#define BELEMS ((size_t)DM*DM)      /* 1M elements per weight matrix */
#define QKV_ELEMS ((size_t)H*BB*SQ*64)
#define CSCALE 0.18033688f          /* log2(e) / sqrt(64) */

// ---------------------------------------------------------------------------
// Scratch (device globals) — activations in fp16, fp32 accumulate in MMAs
// ---------------------------------------------------------------------------
__device__ __align__(256) __half gXh[3*AELEMS];      // QKV inputs
__device__ __align__(256) __half gBh[4*BELEMS];      // weights [n][k] K-major
__device__ __align__(256) __half gQh[QKV_ELEMS];     // [hb][s][64] (pre-scaled by CSCALE)
__device__ __align__(256) __half gKh[QKV_ELEMS];
__device__ __align__(256) __half gVh[QKV_ELEMS];
__device__ __align__(256) __half gOh[AELEMS];        // [s*2+b][h*64+v]

// ---------------------------------------------------------------------------
// PTX helpers (plain sm_103-legal)
// ---------------------------------------------------------------------------
__device__ __forceinline__ uint32_t smem_u32(const void* p) {
    uint32_t a;
    asm("{ .reg .u64 t; cvta.to.shared.u64 t, %1; cvt.u32.u64 %0, t; }" : "=r"(a) : "l"(p));
    return a;
}
__device__ __forceinline__ void cp_async16(uint32_t dst, const void* src) {
    asm volatile("cp.async.cg.shared.global [%0], [%1], 16;" :: "r"(dst), "l"(src));
}
#define CP_COMMIT()  asm volatile("cp.async.commit_group;" ::: "memory")
#define CP_WAIT(N)   asm volatile("cp.async.wait_group %0;" :: "n"(N) : "memory")

__device__ __forceinline__ void ldsm_x4(uint32_t (&r)[4], uint32_t addr) {
    asm volatile("ldmatrix.sync.aligned.m8n8.x4.shared.b16 {%0,%1,%2,%3}, [%4];"
        : "=r"(r[0]), "=r"(r[1]), "=r"(r[2]), "=r"(r[3]) : "r"(addr));
}
__device__ __forceinline__ void ldsm_x4_t(uint32_t (&r)[4], uint32_t addr) {
    asm volatile("ldmatrix.sync.aligned.m8n8.x4.trans.shared.b16 {%0,%1,%2,%3}, [%4];"
        : "=r"(r[0]), "=r"(r[1]), "=r"(r[2]), "=r"(r[3]) : "r"(addr));
}
__device__ __forceinline__ void mma16816(float (&d)[4], const uint32_t (&a)[4],
                                         uint32_t b0, uint32_t b1) {
    asm volatile(
        "mma.sync.aligned.m16n8k16.row.col.f32.f16.f16.f32 "
        "{%0,%1,%2,%3}, {%4,%5,%6,%7}, {%8,%9}, {%0,%1,%2,%3};"
        : "+f"(d[0]), "+f"(d[1]), "+f"(d[2]), "+f"(d[3])
        : "r"(a[0]), "r"(a[1]), "r"(a[2]), "r"(a[3]), "r"(b0), "r"(b1));
}
#define SWZ(o) ((uint32_t)(o) ^ ((((uint32_t)(o)) >> 3) & 0x70))

// exp2 on the MUFU pipe (rel err ~2^-22; -1e4 underflows cleanly to 0)
__device__ __forceinline__ float ex2(float x) {
    float y;
    asm("ex2.approx.f32 %0, %1;" : "=f"(y) : "f"(x));
    return y;
}

__device__ __forceinline__ uint32_t pack_f16(float a, float b) {
    __half2 p = __floats2half2_rn(a, b);
    return *reinterpret_cast<uint32_t*>(&p);
}

// ---------------------------------------------------------------------------
// Merged prep: z<3 -> fp32->fp16 convert of Q/K/V inputs; z>=3 -> weight
// transpose to [n][k] K-major fp16 (z-3: WQ,WK,WV,WO).
// ---------------------------------------------------------------------------
__global__ __launch_bounds__(256) void prep_kernel(const float* __restrict__ Q,
                                                   const float* __restrict__ K,
                                                   const float* __restrict__ V,
                                                   const float* __restrict__ WQ,
                                                   const float* __restrict__ WK,
                                                   const float* __restrict__ WV,
                                                   const float* __restrict__ WO) {
    const int z = blockIdx.z;
    if (z < 3) {
        const float* s = (z == 0) ? Q : (z == 1) ? K : V;
        size_t base = (size_t)(blockIdx.y * 32 + blockIdx.x) * 256 + threadIdx.x;
        #pragma unroll
        for (int t = 0; t < 4; ++t) {
            size_t i = base + (size_t)t * 262144;
            float4 v = ((const float4*)s)[i];
            uint32_t* o = (uint32_t*)gXh + (size_t)z * (AELEMS / 2) + 2 * i;
            o[0] = pack_f16(v.x, v.y);
            o[1] = pack_f16(v.z, v.w);
        }
    } else {
        const int zw = z - 3;
        const float* W = (zw == 0) ? WQ : (zw == 1) ? WK : (zw == 2) ? WV : WO;
        __shared__ float t[32][33];
        const int m0 = blockIdx.x * 32, n0 = blockIdx.y * 32;
        const int tx = threadIdx.x & 31, ty = threadIdx.x >> 5;
        #pragma unroll
        for (int i = 0; i < 4; ++i) {
            int m = m0 + ty + i * 8, n = n0 + tx;
            float v = (zw == 3) ? W[(size_t)m * DM + n]
                                : W[(((size_t)(n >> 6)) * DM + m) * 64 + (n & 63)];
            t[ty + i * 8][tx] = v;
        }
        __syncthreads();
        __half* oh = gBh + (size_t)zw * BELEMS;
        #pragma unroll
        for (int i = 0; i < 4; ++i) {
            int n = n0 + ty + i * 8, m = m0 + tx;
            oh[(size_t)n * DM + m] = __float2half(t[tx][ty + i * 8]);
        }
    }
}

// ---------------------------------------------------------------------------
// fp16 GEMM (HMMA) — R8 pipeline structure (3-stage ring, preload 3, wait(2),
// two syncs per K-stage) + EXPLICIT fragment double-buffering across kk phases
// to hide the ldsm->mma latency chain ptxas wasn't covering (regs 124 -> ~150).
// proj=1: scatter to fp16 q/k/v (Q pre-scaled by CSCALE). proj=0: fp32 Y.
// ---------------------------------------------------------------------------
#define STAGE_BYTES 32768
#define GEMM_SMEM   (1024 + 3*STAGE_BYTES)

__global__ __launch_bounds__(256) void gemm_kernel(float* __restrict__ Yout, int proj) {
    extern __shared__ char smem[];
    const uint32_t sb = (smem_u32(smem) + 1023u) & ~1023u;
    const int tid  = threadIdx.x;
    const int wid  = tid >> 5, lane = tid & 31;
    const int z    = blockIdx.z;
    const int rowBase = blockIdx.x * 128;
    const int nBase   = blockIdx.y * 128;

    const __half* A = proj ? gXh + (size_t)z * AELEMS : gOh;
    const __half* B = gBh + (size_t)(proj ? z : 3) * BELEMS;

    const int wm = (wid >> 2) * 64;
    const int wn = (wid & 3) * 32;
    const int aRow = wm + (lane & 15);
    const int aK   = ((lane >> 4) & 1) * 8;
    const int bRow = wn + (lane & 7) + ((lane >> 4) & 1) * 8;
    const int bK   = ((lane >> 3) & 1) * 8;

    float acc[4][4][4] = {};

    auto load_stage = [&](int buf, int k0) {
        const uint32_t base = sb + buf * STAGE_BYTES;
        #pragma unroll
        for (int j = 0; j < 4; ++j) {
            int idx = tid + j * 256;
            int r = idx >> 3, c = idx & 7;
            uint32_t doff = SWZ(r * 128 + c * 16);
            size_t go = (size_t)r * DM + k0 + c * 8;
            cp_async16(base +         doff, A + (size_t)rowBase * DM + go);
            cp_async16(base + 16384 + doff, B + (size_t)nBase   * DM + go);
        }
        CP_COMMIT();
    };

    load_stage(0, 0);
    load_stage(1, 64);
    load_stage(2, 128);

    for (int it = 0; it < 16; ++it) {
        if (it <= 13)      { CP_WAIT(2); }
        else if (it == 14) { CP_WAIT(1); }
        else               { CP_WAIT(0); }
        __syncthreads();

        const uint32_t bufA = sb + (it % 3) * STAGE_BYTES;
        const uint32_t bufB = bufA + 16384;

        // fragment double-buffer: load kk+1 while kk's MMAs issue
        uint32_t ah[2][4][4], bh[2][2][4];

        auto ldfrag = [&](int kk, uint32_t (&a4)[4][4], uint32_t (&b4)[2][4]) {
            #pragma unroll
            for (int mt = 0; mt < 4; ++mt)
                ldsm_x4(a4[mt], bufA + SWZ(((aRow + mt * 16) * 64 + kk * 16 + aK) * 2));
            #pragma unroll
            for (int np = 0; np < 2; ++np)
                ldsm_x4(b4[np], bufB + SWZ(((bRow + np * 16) * 64 + kk * 16 + bK) * 2));
        };

        ldfrag(0, ah[0], bh[0]);
        #pragma unroll
        for (int kk = 0; kk < 4; ++kk) {
            const int cur = kk & 1;
            if (kk < 3) ldfrag(kk + 1, ah[cur ^ 1], bh[cur ^ 1]);
            #pragma unroll
            for (int mt = 0; mt < 4; ++mt)
                #pragma unroll
                for (int nt = 0; nt < 4; ++nt) {
                    const int np = nt >> 1, q = (nt & 1) * 2;
                    mma16816(acc[mt][nt], ah[cur][mt], bh[cur][np][q], bh[cur][np][q + 1]);
                }
        }
        __syncthreads();
        if (it + 3 < 16) load_stage(it % 3, (it + 3) * 64);
    }

    const float qscale = (proj && z == 0) ? CSCALE : 1.0f;

    #pragma unroll
    for (int mt = 0; mt < 4; ++mt)
        #pragma unroll
        for (int nt = 0; nt < 4; ++nt) {
            int r = rowBase + wm + mt * 16 + (lane >> 2);
            int n = nBase + wn + nt * 8 + (lane & 3) * 2;
            float* a4 = acc[mt][nt];
            if (proj) {
                __half* oh = (z == 0) ? gQh : (z == 1) ? gKh : gVh;
                int h = n >> 6, k = n & 63, b = r & 1, s = r >> 1;
                size_t i0 = (((size_t)h * BB + b) * SQ + s) * 64 + k;
                size_t i1 = i0 + 4 * 64;   // row r+8 -> s+4
                *(uint32_t*)(oh + i0) = pack_f16(a4[0] * qscale, a4[1] * qscale);
                *(uint32_t*)(oh + i1) = pack_f16(a4[2] * qscale, a4[3] * qscale);
            } else {
                *(float2*)(Yout + (size_t)r * DM + n)       = make_float2(a4[0], a4[1]);
                *(float2*)(Yout + (size_t)(r + 8) * DM + n) = make_float2(a4[2], a4[3]);
            }
        }
}

// ---------------------------------------------------------------------------
// fp16 tensor-core causal flash attention (R12 champion version):
// maxless softmax, exp on MUFU, row-sums via MMA, mask inside loop.
// CTA: 128 threads, 64 queries; 3-stage KV ring; 3 CTAs/SM.
// ---------------------------------------------------------------------------
#define ATT_QBYTES 8192             /* Q fp16 tile                       */
#define ATT_STAGE  16384            /* K 8K | V 8K                       */
#define ATT_SMEM   (1024 + ATT_QBYTES + 3*ATT_STAGE)
#define ONES2 0x3C003C00u           /* half2(1,1) */

__global__ __launch_bounds__(128, 3) void attn_kernel()
{
    extern __shared__ char smem[];
    const uint32_t sb  = (smem_u32(smem) + 1023u) & ~1023u;
    const uint32_t skv = sb + ATT_QBYTES;
    const int tid  = threadIdx.x;
    const int wid  = tid >> 5, lane = tid & 31;
    const int qt   = (int)gridDim.x - 1 - (int)blockIdx.x;   // heavy first
    const int hb   = blockIdx.y;
    const int hh   = hb >> 1, bb = hb & 1;
    const int wm   = wid * 16;

    const __half* qp = gQh + (size_t)hb * SQ * 64;
    const __half* kp = gKh + (size_t)hb * SQ * 64;
    const __half* vp = gVh + (size_t)hb * SQ * 64;

    const int rL = lane & 15;            // ldmatrix row part
    const int cL = (lane >> 4) * 8;      // ldmatrix col part
    const int nk = qt + 1;

    auto loadKV = [&](int buf, int kt) {
        const uint32_t base = skv + buf * ATT_STAGE;
        #pragma unroll
        for (int t2 = 0; t2 < 4; ++t2) {
            int c = tid + t2 * 128;          // 512 chunks per tensor
            int r = c >> 3, cc = c & 7;
            uint32_t doff = SWZ(r * 128 + cc * 16);
            size_t go = (size_t)(kt * 64 + r) * 64 + cc * 8;
            cp_async16(base +        doff, kp + go);
            cp_async16(base + 8192 + doff, vp + go);
        }
        CP_COMMIT();
    };

    // ---- issue Q group + first two KV groups, then build Q fragments ----
    uint32_t qh[4][4];
    {
        #pragma unroll
        for (int t2 = 0; t2 < 4; ++t2) {
            int c = tid + t2 * 128;          // 512 chunks
            int r = c >> 3, cc = c & 7;
            uint32_t doff = SWZ(r * 128 + cc * 16);
            cp_async16(sb + doff, qp + (size_t)(qt * 64 + r) * 64 + cc * 8);
        }
        CP_COMMIT();
        loadKV(0, 0);
        if (nk > 1) { loadKV(1, 1); CP_WAIT(2); } else { CP_WAIT(1); }
        __syncthreads();
        #pragma unroll
        for (int kk = 0; kk < 4; ++kk) {
            uint32_t off = SWZ((wm + rL) * 128 + (kk * 16 + cL) * 2);
            ldsm_x4(qh[kk], sb + off);
        }
    }

    float o[8][4] = {};
    float rs[4] = {};                        // row-sum accumulator (via MMA)
    const int row0 = qt * 64 + wm + (lane >> 2);
    const int row1 = row0 + 8;

    for (int kt = 0; kt < nk; ++kt) {
        if (kt + 1 < nk) { CP_WAIT(1); } else { CP_WAIT(0); }
        __syncthreads();
        if (kt + 2 < nk) loadKV((kt + 2) % 3, kt + 2);

        const uint32_t stK = skv + (kt % 3) * ATT_STAGE;
        const uint32_t stV = stK + 8192;

        // ---- S = Q K^T (fp16, fp32 acc); C pre-folded into Q ----
        float s[8][4] = {};
        #pragma unroll
        for (int kk = 0; kk < 4; ++kk) {
            #pragma unroll
            for (int np = 0; np < 4; ++np) {
                uint32_t off = SWZ((np * 16 + rL) * 128 + (kk * 16 + cL) * 2);
                uint32_t kh4[4];
                ldsm_x4(kh4, stK + off);
                mma16816(s[2*np],   qh[kk], kh4[0], kh4[2]);
                mma16816(s[2*np+1], qh[kk], kh4[1], kh4[3]);
            }
        }

        // ---- causal mask on the diagonal tile only ----
        if (kt == qt) {
            #pragma unroll
            for (int j = 0; j < 8; ++j) {
                int colb = kt * 64 + j * 8 + (lane & 3) * 2;
                if (colb     > row0) s[j][0] = -1e4f;
                if (colb + 1 > row0) s[j][1] = -1e4f;
                if (colb     > row1) s[j][2] = -1e4f;
                if (colb + 1 > row1) s[j][3] = -1e4f;
            }
        }

        // ---- maxless softmax: exp2 on MUFU, pack P, row-sums via MMA ----
        uint32_t ph[4][4];
        #pragma unroll
        for (int kk = 0; kk < 4; ++kk) {
            #pragma unroll
            for (int q = 0; q < 4; ++q) {
                float a = ex2(s[2*kk + (q >> 1)][(q & 1) * 2]);
                float b = ex2(s[2*kk + (q >> 1)][(q & 1) * 2 + 1]);
                ph[kk][q] = pack_f16(a, b);
            }
            mma16816(rs, ph[kk], ONES2, ONES2);   // rs[0]=row0 sum, rs[2]=row1 sum
        }

        // ---- O += P V (fp16, fp32 acc) ----
        #pragma unroll
        for (int kk = 0; kk < 4; ++kk) {
            #pragma unroll
            for (int np = 0; np < 4; ++np) {
                uint32_t off = SWZ((kk * 16 + rL) * 128 + (np * 16 + cL) * 2);
                uint32_t vh4[4];
                ldsm_x4_t(vh4, stV + off);
                mma16816(o[2*np],   ph[kk], vh4[0], vh4[1]);
                mma16816(o[2*np+1], ph[kk], vh4[2], vh4[3]);
            }
        }
    }

    // ---- finalize, write fp16 O (per-row sums; no shfl needed) ----
    const float inv0 = 1.f / rs[0], inv1 = 1.f / rs[2];
    const size_t or0 = (size_t)(row0 * 2 + bb) * DM;
    const size_t or1 = (size_t)(row1 * 2 + bb) * DM;
    #pragma unroll
    for (int j = 0; j < 8; ++j) {
        int vc = hh * 64 + j * 8 + (lane & 3) * 2;
        *(uint32_t*)(gOh + or0 + vc) = pack_f16(o[j][0] * inv0, o[j][1] * inv0);
        *(uint32_t*)(gOh + or1 + vc) = pack_f16(o[j][2] * inv1, o[j][3] * inv1);
    }
}

// ---------------------------------------------------------------------------
extern "C" void kernel_launch(void* const* d_in, const int* in_sizes, int n_in,
                              void* d_out, int out_size)
{
    (void)in_sizes; (void)n_in; (void)out_size;
    const float* Q  = (const float*)d_in[0];
    const float* K  = (const float*)d_in[1];
    const float* V  = (const float*)d_in[2];
    const float* WQ = (const float*)d_in[3];
    const float* WK = (const float*)d_in[4];
    const float* WV = (const float*)d_in[5];
    const float* WO = (const float*)d_in[6];
    float* Y = (float*)d_out;

    static int smem_set = 0;
    if (!smem_set) {
        cudaFuncSetAttribute(gemm_kernel, cudaFuncAttributeMaxDynamicSharedMemorySize, GEMM_SMEM);
        cudaFuncSetAttribute(attn_kernel, cudaFuncAttributeMaxDynamicSharedMemorySize, ATT_SMEM);
        smem_set = 1;
    }

    prep_kernel<<<dim3(32, 32, 7), 256>>>(Q, K, V, WQ, WK, WV, WO);

    gemm_kernel<<<dim3(32, 8, 3), 256, GEMM_SMEM>>>(nullptr, 1);   // QKV proj

    attn_kernel<<<dim3(SQ/64, H*BB), 128, ATT_SMEM>>>();           // flash attention

    gemm_kernel<<<dim3(32, 8, 1), 256, GEMM_SMEM>>>(Y, 0);         // out proj
}

// round 16
// speedup vs baseline: 1.0526x; 1.0526x over previous
#include <cuda_runtime.h>
#include <cuda_fp16.h>
#include <math.h>
#include <stdint.h>

#define H   16
#define DM  1024
#define DK  64
#define DV  64
#define SQ  2048
#define BB  2
#define NR  (SQ*BB)                 /* 4096 rows */
#define AELEMS ((size_t)NR*DM)      /* 4M elements per activation tensor */
#define BELEMS ((size_t)DM*DM)      /* 1M elements per weight matrix */
#define QKV_ELEMS ((size_t)H*BB*SQ*64)
#define CSCALE 0.18033688f          /* log2(e) / sqrt(64) */

// ---------------------------------------------------------------------------
// Scratch (device globals) — activations in fp16, fp32 accumulate in MMAs
// ---------------------------------------------------------------------------
__device__ __align__(256) __half gXh[3*AELEMS];      // QKV inputs
__device__ __align__(256) __half gBh[4*BELEMS];      // weights [n][k] K-major
__device__ __align__(256) __half gQh[QKV_ELEMS];     // [hb][s][64] (CSCALE folded into WQ)
__device__ __align__(256) __half gKh[QKV_ELEMS];
__device__ __align__(256) __half gVh[QKV_ELEMS];
__device__ __align__(256) __half gOh[AELEMS];        // [s*2+b][h*64+v]

// ---------------------------------------------------------------------------
// PTX helpers (plain sm_103-legal)
// ---------------------------------------------------------------------------
__device__ __forceinline__ uint32_t smem_u32(const void* p) {
    uint32_t a;
    asm("{ .reg .u64 t; cvta.to.shared.u64 t, %1; cvt.u32.u64 %0, t; }" : "=r"(a) : "l"(p));
    return a;
}
__device__ __forceinline__ void cp_async16(uint32_t dst, const void* src) {
    asm volatile("cp.async.cg.shared.global [%0], [%1], 16;" :: "r"(dst), "l"(src));
}
#define CP_COMMIT()  asm volatile("cp.async.commit_group;" ::: "memory")
#define CP_WAIT(N)   asm volatile("cp.async.wait_group %0;" :: "n"(N) : "memory")

__device__ __forceinline__ void ldsm_x4(uint32_t (&r)[4], uint32_t addr) {
    asm volatile("ldmatrix.sync.aligned.m8n8.x4.shared.b16 {%0,%1,%2,%3}, [%4];"
        : "=r"(r[0]), "=r"(r[1]), "=r"(r[2]), "=r"(r[3]) : "r"(addr));
}
__device__ __forceinline__ void ldsm_x4_t(uint32_t (&r)[4], uint32_t addr) {
    asm volatile("ldmatrix.sync.aligned.m8n8.x4.trans.shared.b16 {%0,%1,%2,%3}, [%4];"
        : "=r"(r[0]), "=r"(r[1]), "=r"(r[2]), "=r"(r[3]) : "r"(addr));
}
__device__ __forceinline__ void mma16816(float (&d)[4], const uint32_t (&a)[4],
                                         uint32_t b0, uint32_t b1) {
    asm volatile(
        "mma.sync.aligned.m16n8k16.row.col.f32.f16.f16.f32 "
        "{%0,%1,%2,%3}, {%4,%5,%6,%7}, {%8,%9}, {%0,%1,%2,%3};"
        : "+f"(d[0]), "+f"(d[1]), "+f"(d[2]), "+f"(d[3])
        : "r"(a[0]), "r"(a[1]), "r"(a[2]), "r"(a[3]), "r"(b0), "r"(b1));
}
#define SWZ(o) ((uint32_t)(o) ^ ((((uint32_t)(o)) >> 3) & 0x70))

// exp2 on the MUFU pipe (rel err ~2^-22; -1e4 underflows cleanly to 0)
__device__ __forceinline__ float ex2(float x) {
    float y;
    asm("ex2.approx.f32 %0, %1;" : "=f"(y) : "f"(x));
    return y;
}

__device__ __forceinline__ uint32_t pack_f16(float a, float b) {
    __half2 p = __floats2half2_rn(a, b);
    return *reinterpret_cast<uint32_t*>(&p);
}

// ---------------------------------------------------------------------------
// Merged prep: z<3 -> fp32->fp16 convert of Q/K/V inputs; z>=3 -> weight
// transpose to [n][k] K-major fp16 (z-3: WQ,WK,WV,WO). CSCALE folded into WQ.
// ---------------------------------------------------------------------------
__global__ __launch_bounds__(256) void prep_kernel(const float* __restrict__ Q,
                                                   const float* __restrict__ K,
                                                   const float* __restrict__ V,
                                                   const float* __restrict__ WQ,
                                                   const float* __restrict__ WK,
                                                   const float* __restrict__ WV,
                                                   const float* __restrict__ WO) {
    const int z = blockIdx.z;
    if (z < 3) {
        const float* s = (z == 0) ? Q : (z == 1) ? K : V;
        size_t base = (size_t)(blockIdx.y * 32 + blockIdx.x) * 256 + threadIdx.x;
        #pragma unroll
        for (int t = 0; t < 4; ++t) {
            size_t i = base + (size_t)t * 262144;
            float4 v = ((const float4*)s)[i];
            uint32_t* o = (uint32_t*)gXh + (size_t)z * (AELEMS / 2) + 2 * i;
            o[0] = pack_f16(v.x, v.y);
            o[1] = pack_f16(v.z, v.w);
        }
    } else {
        const int zw = z - 3;
        const float* W = (zw == 0) ? WQ : (zw == 1) ? WK : (zw == 2) ? WV : WO;
        const float wscale = (zw == 0) ? CSCALE : 1.0f;   // fold softmax scale into WQ
        __shared__ float t[32][33];
        const int m0 = blockIdx.x * 32, n0 = blockIdx.y * 32;
        const int tx = threadIdx.x & 31, ty = threadIdx.x >> 5;
        #pragma unroll
        for (int i = 0; i < 4; ++i) {
            int m = m0 + ty + i * 8, n = n0 + tx;
            float v = (zw == 3) ? W[(size_t)m * DM + n]
                                : W[(((size_t)(n >> 6)) * DM + m) * 64 + (n & 63)];
            t[ty + i * 8][tx] = v * wscale;
        }
        __syncthreads();
        __half* oh = gBh + (size_t)zw * BELEMS;
        #pragma unroll
        for (int i = 0; i < 4; ++i) {
            int n = n0 + ty + i * 8, m = m0 + tx;
            oh[(size_t)n * DM + m] = __float2half(t[tx][ty + i * 8]);
        }
    }
}

// ---------------------------------------------------------------------------
// fp16 GEMM (HMMA) — FROZEN R8/R12 structure (3-stage ring, preload 3,
// wait(2), two syncs per K-stage, no reg cap, 99KB smem).
// proj=1: scatter to fp16 q/k/v. proj=0: fp32 Y. Branchless epilogue scale.
// ---------------------------------------------------------------------------
#define STAGE_BYTES 32768
#define GEMM_SMEM   (1024 + 3*STAGE_BYTES)

__global__ __launch_bounds__(256) void gemm_kernel(float* __restrict__ Yout, int proj) {
    extern __shared__ char smem[];
    const uint32_t sb = (smem_u32(smem) + 1023u) & ~1023u;
    const int tid  = threadIdx.x;
    const int wid  = tid >> 5, lane = tid & 31;
    const int z    = blockIdx.z;
    const int rowBase = blockIdx.x * 128;
    const int nBase   = blockIdx.y * 128;

    const __half* A = proj ? gXh + (size_t)z * AELEMS : gOh;
    const __half* B = gBh + (size_t)(proj ? z : 3) * BELEMS;

    const int wm = (wid >> 2) * 64;
    const int wn = (wid & 3) * 32;
    const int aRow = wm + (lane & 15);
    const int aK   = ((lane >> 4) & 1) * 8;
    const int bRow = wn + (lane & 7) + ((lane >> 4) & 1) * 8;
    const int bK   = ((lane >> 3) & 1) * 8;

    float acc[4][4][4] = {};

    auto load_stage = [&](int buf, int k0) {
        const uint32_t base = sb + buf * STAGE_BYTES;
        #pragma unroll
        for (int j = 0; j < 4; ++j) {
            int idx = tid + j * 256;
            int r = idx >> 3, c = idx & 7;
            uint32_t doff = SWZ(r * 128 + c * 16);
            size_t go = (size_t)r * DM + k0 + c * 8;
            cp_async16(base +         doff, A + (size_t)rowBase * DM + go);
            cp_async16(base + 16384 + doff, B + (size_t)nBase   * DM + go);
        }
        CP_COMMIT();
    };

    load_stage(0, 0);
    load_stage(1, 64);
    load_stage(2, 128);

    for (int it = 0; it < 16; ++it) {
        if (it <= 13)      { CP_WAIT(2); }
        else if (it == 14) { CP_WAIT(1); }
        else               { CP_WAIT(0); }
        __syncthreads();

        const uint32_t bufA = sb + (it % 3) * STAGE_BYTES;
        const uint32_t bufB = bufA + 16384;

        #pragma unroll
        for (int kk = 0; kk < 4; ++kk) {
            uint32_t ah[4][4], bh[2][4];
            #pragma unroll
            for (int mt = 0; mt < 4; ++mt) {
                uint32_t off = SWZ(((aRow + mt * 16) * 64 + kk * 16 + aK) * 2);
                ldsm_x4(ah[mt], bufA + off);
            }
            #pragma unroll
            for (int np = 0; np < 2; ++np) {
                uint32_t off = SWZ(((bRow + np * 16) * 64 + kk * 16 + bK) * 2);
                ldsm_x4(bh[np], bufB + off);
            }
            #pragma unroll
            for (int mt = 0; mt < 4; ++mt)
                #pragma unroll
                for (int nt = 0; nt < 4; ++nt) {
                    const int np = nt >> 1, q = (nt & 1) * 2;
                    mma16816(acc[mt][nt], ah[mt], bh[np][q], bh[np][q + 1]);
                }
        }
        __syncthreads();
        if (it + 3 < 16) load_stage(it % 3, (it + 3) * 64);
    }

    #pragma unroll
    for (int mt = 0; mt < 4; ++mt)
        #pragma unroll
        for (int nt = 0; nt < 4; ++nt) {
            int r = rowBase + wm + mt * 16 + (lane >> 2);
            int n = nBase + wn + nt * 8 + (lane & 3) * 2;
            float* a4 = acc[mt][nt];
            if (proj) {
                __half* oh = (z == 0) ? gQh : (z == 1) ? gKh : gVh;
                int h = n >> 6, k = n & 63, b = r & 1, s = r >> 1;
                size_t i0 = (((size_t)h * BB + b) * SQ + s) * 64 + k;
                size_t i1 = i0 + 4 * 64;   // row r+8 -> s+4
                *(uint32_t*)(oh + i0) = pack_f16(a4[0], a4[1]);
                *(uint32_t*)(oh + i1) = pack_f16(a4[2], a4[3]);
            } else {
                *(float2*)(Yout + (size_t)r * DM + n)       = make_float2(a4[0], a4[1]);
                *(float2*)(Yout + (size_t)(r + 8) * DM + n) = make_float2(a4[2], a4[3]);
            }
        }
}

// ---------------------------------------------------------------------------
// fp16 tensor-core causal flash attention (R12 champion version):
// maxless softmax, exp on MUFU, row-sums via MMA, mask inside loop.
// CTA: 128 threads, 64 queries; 3-stage KV ring; 3 CTAs/SM.
// ---------------------------------------------------------------------------
#define ATT_QBYTES 8192             /* Q fp16 tile                       */
#define ATT_STAGE  16384            /* K 8K | V 8K                       */
#define ATT_SMEM   (1024 + ATT_QBYTES + 3*ATT_STAGE)
#define ONES2 0x3C003C00u           /* half2(1,1) */

__global__ __launch_bounds__(128, 3) void attn_kernel()
{
    extern __shared__ char smem[];
    const uint32_t sb  = (smem_u32(smem) + 1023u) & ~1023u;
    const uint32_t skv = sb + ATT_QBYTES;
    const int tid  = threadIdx.x;
    const int wid  = tid >> 5, lane = tid & 31;
    const int qt   = (int)gridDim.x - 1 - (int)blockIdx.x;   // heavy first
    const int hb   = blockIdx.y;
    const int hh   = hb >> 1, bb = hb & 1;
    const int wm   = wid * 16;

    const __half* qp = gQh + (size_t)hb * SQ * 64;
    const __half* kp = gKh + (size_t)hb * SQ * 64;
    const __half* vp = gVh + (size_t)hb * SQ * 64;

    const int rL = lane & 15;            // ldmatrix row part
    const int cL = (lane >> 4) * 8;      // ldmatrix col part
    const int nk = qt + 1;

    auto loadKV = [&](int buf, int kt) {
        const uint32_t base = skv + buf * ATT_STAGE;
        #pragma unroll
        for (int t2 = 0; t2 < 4; ++t2) {
            int c = tid + t2 * 128;          // 512 chunks per tensor
            int r = c >> 3, cc = c & 7;
            uint32_t doff = SWZ(r * 128 + cc * 16);
            size_t go = (size_t)(kt * 64 + r) * 64 + cc * 8;
            cp_async16(base +        doff, kp + go);
            cp_async16(base + 8192 + doff, vp + go);
        }
        CP_COMMIT();
    };

    // ---- issue Q group + first two KV groups, then build Q fragments ----
    uint32_t qh[4][4];
    {
        #pragma unroll
        for (int t2 = 0; t2 < 4; ++t2) {
            int c = tid + t2 * 128;          // 512 chunks
            int r = c >> 3, cc = c & 7;
            uint32_t doff = SWZ(r * 128 + cc * 16);
            cp_async16(sb + doff, qp + (size_t)(qt * 64 + r) * 64 + cc * 8);
        }
        CP_COMMIT();
        loadKV(0, 0);
        if (nk > 1) { loadKV(1, 1); CP_WAIT(2); } else { CP_WAIT(1); }
        __syncthreads();
        #pragma unroll
        for (int kk = 0; kk < 4; ++kk) {
            uint32_t off = SWZ((wm + rL) * 128 + (kk * 16 + cL) * 2);
            ldsm_x4(qh[kk], sb + off);
        }
    }

    float o[8][4] = {};
    float rs[4] = {};                        // row-sum accumulator (via MMA)
    const int row0 = qt * 64 + wm + (lane >> 2);
    const int row1 = row0 + 8;

    for (int kt = 0; kt < nk; ++kt) {
        if (kt + 1 < nk) { CP_WAIT(1); } else { CP_WAIT(0); }
        __syncthreads();
        if (kt + 2 < nk) loadKV((kt + 2) % 3, kt + 2);

        const uint32_t stK = skv + (kt % 3) * ATT_STAGE;
        const uint32_t stV = stK + 8192;

        // ---- S = Q K^T (fp16, fp32 acc); scale pre-folded into WQ ----
        float s[8][4] = {};
        #pragma unroll
        for (int kk = 0; kk < 4; ++kk) {
            #pragma unroll
            for (int np = 0; np < 4; ++np) {
                uint32_t off = SWZ((np * 16 + rL) * 128 + (kk * 16 + cL) * 2);
                uint32_t kh4[4];
                ldsm_x4(kh4, stK + off);
                mma16816(s[2*np],   qh[kk], kh4[0], kh4[2]);
                mma16816(s[2*np+1], qh[kk], kh4[1], kh4[3]);
            }
        }

        // ---- causal mask on the diagonal tile only ----
        if (kt == qt) {
            #pragma unroll
            for (int j = 0; j < 8; ++j) {
                int colb = kt * 64 + j * 8 + (lane & 3) * 2;
                if (colb     > row0) s[j][0] = -1e4f;
                if (colb + 1 > row0) s[j][1] = -1e4f;
                if (colb     > row1) s[j][2] = -1e4f;
                if (colb + 1 > row1) s[j][3] = -1e4f;
            }
        }

        // ---- maxless softmax: exp2 on MUFU, pack P, row-sums via MMA ----
        uint32_t ph[4][4];
        #pragma unroll
        for (int kk = 0; kk < 4; ++kk) {
            #pragma unroll
            for (int q = 0; q < 4; ++q) {
                float a = ex2(s[2*kk + (q >> 1)][(q & 1) * 2]);
                float b = ex2(s[2*kk + (q >> 1)][(q & 1) * 2 + 1]);
                ph[kk][q] = pack_f16(a, b);
            }
            mma16816(rs, ph[kk], ONES2, ONES2);   // rs[0]=row0 sum, rs[2]=row1 sum
        }

        // ---- O += P V (fp16, fp32 acc) ----
        #pragma unroll
        for (int kk = 0; kk < 4; ++kk) {
            #pragma unroll
            for (int np = 0; np < 4; ++np) {
                uint32_t off = SWZ((kk * 16 + rL) * 128 + (np * 16 + cL) * 2);
                uint32_t vh4[4];
                ldsm_x4_t(vh4, stV + off);
                mma16816(o[2*np],   ph[kk], vh4[0], vh4[1]);
                mma16816(o[2*np+1], ph[kk], vh4[2], vh4[3]);
            }
        }
    }

    // ---- finalize, write fp16 O (per-row sums; no shfl needed) ----
    const float inv0 = 1.f / rs[0], inv1 = 1.f / rs[2];
    const size_t or0 = (size_t)(row0 * 2 + bb) * DM;
    const size_t or1 = (size_t)(row1 * 2 + bb) * DM;
    #pragma unroll
    for (int j = 0; j < 8; ++j) {
        int vc = hh * 64 + j * 8 + (lane & 3) * 2;
        *(uint32_t*)(gOh + or0 + vc) = pack_f16(o[j][0] * inv0, o[j][1] * inv0);
        *(uint32_t*)(gOh + or1 + vc) = pack_f16(o[j][2] * inv1, o[j][3] * inv1);
    }
}

// ---------------------------------------------------------------------------
extern "C" void kernel_launch(void* const* d_in, const int* in_sizes, int n_in,
                              void* d_out, int out_size)
{
    (void)in_sizes; (void)n_in; (void)out_size;
    const float* Q  = (const float*)d_in[0];
    const float* K  = (const float*)d_in[1];
    const float* V  = (const float*)d_in[2];
    const float* WQ = (const float*)d_in[3];
    const float* WK = (const float*)d_in[4];
    const float* WV = (const float*)d_in[5];
    const float* WO = (const float*)d_in[6];
    float* Y = (float*)d_out;

    static int smem_set = 0;
    if (!smem_set) {
        cudaFuncSetAttribute(gemm_kernel, cudaFuncAttributeMaxDynamicSharedMemorySize, GEMM_SMEM);
        cudaFuncSetAttribute(attn_kernel, cudaFuncAttributeMaxDynamicSharedMemorySize, ATT_SMEM);
        smem_set = 1;
    }

    prep_kernel<<<dim3(32, 32, 7), 256>>>(Q, K, V, WQ, WK, WV, WO);

    gemm_kernel<<<dim3(32, 8, 3), 256, GEMM_SMEM>>>(nullptr, 1);   // QKV proj

    attn_kernel<<<dim3(SQ/64, H*BB), 128, ATT_SMEM>>>();           // flash attention

    gemm_kernel<<<dim3(32, 8, 1), 256, GEMM_SMEM>>>(Y, 0);         // out proj
}

// round 17
// speedup vs baseline: 1.0868x; 1.0325x over previous
#include <cuda_runtime.h>
#include <cuda_fp16.h>
#include <math.h>
#include <stdint.h>

#define H   16
#define DM  1024
#define DK  64
#define DV  64
#define SQ  2048
#define BB  2
#define NR  (SQ*BB)                 /* 4096 rows */
#define AELEMS ((size_t)NR*DM)      /* 4M elements per activation tensor */
#define BELEMS ((size_t)DM*DM)      /* 1M elements per weight matrix */
#define QKV_ELEMS ((size_t)H*BB*SQ*64)
#define CSCALE 0.18033688f          /* log2(e) / sqrt(64) */

// ---------------------------------------------------------------------------
// Scratch (device globals) — activations in fp16, fp32 accumulate in MMAs
// ---------------------------------------------------------------------------
__device__ __align__(256) __half gXh[3*AELEMS];      // QKV inputs
__device__ __align__(256) __half gBh[4*BELEMS];      // weights [n][k] K-major
__device__ __align__(256) __half gQh[QKV_ELEMS];     // [hb][s][64] (CSCALE folded into WQ)
__device__ __align__(256) __half gKh[QKV_ELEMS];
__device__ __align__(256) __half gVh[QKV_ELEMS];
__device__ __align__(256) __half gOh[AELEMS];        // [s*2+b][h*64+v]

// ---------------------------------------------------------------------------
// PTX helpers (plain sm_103-legal)
// ---------------------------------------------------------------------------
__device__ __forceinline__ uint32_t smem_u32(const void* p) {
    uint32_t a;
    asm("{ .reg .u64 t; cvta.to.shared.u64 t, %1; cvt.u32.u64 %0, t; }" : "=r"(a) : "l"(p));
    return a;
}
__device__ __forceinline__ void cp_async16(uint32_t dst, const void* src) {
    asm volatile("cp.async.cg.shared.global [%0], [%1], 16;" :: "r"(dst), "l"(src));
}
#define CP_COMMIT()  asm volatile("cp.async.commit_group;" ::: "memory")
#define CP_WAIT(N)   asm volatile("cp.async.wait_group %0;" :: "n"(N) : "memory")

__device__ __forceinline__ void ldsm_x4(uint32_t (&r)[4], uint32_t addr) {
    asm volatile("ldmatrix.sync.aligned.m8n8.x4.shared.b16 {%0,%1,%2,%3}, [%4];"
        : "=r"(r[0]), "=r"(r[1]), "=r"(r[2]), "=r"(r[3]) : "r"(addr));
}
__device__ __forceinline__ void ldsm_x4_t(uint32_t (&r)[4], uint32_t addr) {
    asm volatile("ldmatrix.sync.aligned.m8n8.x4.trans.shared.b16 {%0,%1,%2,%3}, [%4];"
        : "=r"(r[0]), "=r"(r[1]), "=r"(r[2]), "=r"(r[3]) : "r"(addr));
}
__device__ __forceinline__ void mma16816(float (&d)[4], const uint32_t (&a)[4],
                                         uint32_t b0, uint32_t b1) {
    asm volatile(
        "mma.sync.aligned.m16n8k16.row.col.f32.f16.f16.f32 "
        "{%0,%1,%2,%3}, {%4,%5,%6,%7}, {%8,%9}, {%0,%1,%2,%3};"
        : "+f"(d[0]), "+f"(d[1]), "+f"(d[2]), "+f"(d[3])
        : "r"(a[0]), "r"(a[1]), "r"(a[2]), "r"(a[3]), "r"(b0), "r"(b1));
}
#define SWZ(o) ((uint32_t)(o) ^ ((((uint32_t)(o)) >> 3) & 0x70))

// exp2 on the MUFU pipe (rel err ~2^-22; -1e4 underflows cleanly to 0)
__device__ __forceinline__ float ex2(float x) {
    float y;
    asm("ex2.approx.f32 %0, %1;" : "=f"(y) : "f"(x));
    return y;
}

__device__ __forceinline__ uint32_t pack_f16(float a, float b) {
    __half2 p = __floats2half2_rn(a, b);
    return *reinterpret_cast<uint32_t*>(&p);
}

// ---------------------------------------------------------------------------
// Merged prep: z<3 -> fp32->fp16 convert of Q/K/V inputs; z>=3 -> weight
// transpose to [n][k] K-major fp16 (z-3: WQ,WK,WV,WO). CSCALE folded into WQ.
// ---------------------------------------------------------------------------
__global__ __launch_bounds__(256) void prep_kernel(const float* __restrict__ Q,
                                                   const float* __restrict__ K,
                                                   const float* __restrict__ V,
                                                   const float* __restrict__ WQ,
                                                   const float* __restrict__ WK,
                                                   const float* __restrict__ WV,
                                                   const float* __restrict__ WO) {
    const int z = blockIdx.z;
    if (z < 3) {
        const float* s = (z == 0) ? Q : (z == 1) ? K : V;
        size_t base = (size_t)(blockIdx.y * 32 + blockIdx.x) * 256 + threadIdx.x;
        #pragma unroll
        for (int t = 0; t < 4; ++t) {
            size_t i = base + (size_t)t * 262144;
            float4 v = ((const float4*)s)[i];
            uint32_t* o = (uint32_t*)gXh + (size_t)z * (AELEMS / 2) + 2 * i;
            o[0] = pack_f16(v.x, v.y);
            o[1] = pack_f16(v.z, v.w);
        }
    } else {
        const int zw = z - 3;
        const float* W = (zw == 0) ? WQ : (zw == 1) ? WK : (zw == 2) ? WV : WO;
        const float wscale = (zw == 0) ? CSCALE : 1.0f;   // fold softmax scale into WQ
        __shared__ float t[32][33];
        const int m0 = blockIdx.x * 32, n0 = blockIdx.y * 32;
        const int tx = threadIdx.x & 31, ty = threadIdx.x >> 5;
        #pragma unroll
        for (int i = 0; i < 4; ++i) {
            int m = m0 + ty + i * 8, n = n0 + tx;
            float v = (zw == 3) ? W[(size_t)m * DM + n]
                                : W[(((size_t)(n >> 6)) * DM + m) * 64 + (n & 63)];
            t[ty + i * 8][tx] = v * wscale;
        }
        __syncthreads();
        __half* oh = gBh + (size_t)zw * BELEMS;
        #pragma unroll
        for (int i = 0; i < 4; ++i) {
            int n = n0 + ty + i * 8, m = m0 + tx;
            oh[(size_t)n * DM + m] = __float2half(t[tx][ty + i * 8]);
        }
    }
}

// ---------------------------------------------------------------------------
// fp16 GEMM (HMMA) — R8 ring schedule (preload 3, wait(2), two syncs) kept
// bit-for-bit; CTA shrunk to 128 threads / 128x64 tile so 3 CTAs fit per SM
// at natural register count (no cap, no spills). 4 warps, 2x2 warp grid,
// warp tile 64x32. Stage = A 16KB + B 8KB; 3-stage ring = 73KB smem.
// proj=1: scatter to fp16 q/k/v. proj=0: fp32 Y.
// ---------------------------------------------------------------------------
#define A_BYTES 16384               /* 128 x 64 fp16 */
#define B_BYTES 8192                /*  64 x 64 fp16 */
#define STAGE_BYTES (A_BYTES + B_BYTES)
#define GEMM_SMEM   (1024 + 3*STAGE_BYTES)

__global__ __launch_bounds__(128, 3) void gemm_kernel(float* __restrict__ Yout, int proj) {
    extern __shared__ char smem[];
    const uint32_t sb = (smem_u32(smem) + 1023u) & ~1023u;
    const int tid  = threadIdx.x;
    const int wid  = tid >> 5, lane = tid & 31;
    const int z    = blockIdx.z;
    const int rowBase = blockIdx.x * 128;
    const int nBase   = blockIdx.y * 64;

    const __half* A = proj ? gXh + (size_t)z * AELEMS : gOh;
    const __half* B = gBh + (size_t)(proj ? z : 3) * BELEMS;

    const int wm = (wid >> 1) * 64;          // 0 or 64
    const int wn = (wid & 1) * 32;           // 0 or 32
    const int aRow = wm + (lane & 15);
    const int aK   = ((lane >> 4) & 1) * 8;
    const int bRow = wn + (lane & 7) + ((lane >> 4) & 1) * 8;
    const int bK   = ((lane >> 3) & 1) * 8;

    float acc[4][4][4] = {};

    auto load_stage = [&](int buf, int k0) {
        const uint32_t base = sb + buf * STAGE_BYTES;
        // A: 128x64 fp16 = 1024 chunks of 16B
        #pragma unroll
        for (int j = 0; j < 8; ++j) {
            int idx = tid + j * 128;
            int r = idx >> 3, c = idx & 7;
            uint32_t doff = SWZ(r * 128 + c * 16);
            cp_async16(base + doff, A + (size_t)(rowBase + r) * DM + k0 + c * 8);
        }
        // B: 64x64 fp16 = 512 chunks of 16B
        #pragma unroll
        for (int j = 0; j < 4; ++j) {
            int idx = tid + j * 128;
            int r = idx >> 3, c = idx & 7;
            uint32_t doff = SWZ(r * 128 + c * 16);
            cp_async16(base + A_BYTES + doff, B + (size_t)(nBase + r) * DM + k0 + c * 8);
        }
        CP_COMMIT();
    };

    load_stage(0, 0);
    load_stage(1, 64);
    load_stage(2, 128);

    for (int it = 0; it < 16; ++it) {
        if (it <= 13)      { CP_WAIT(2); }
        else if (it == 14) { CP_WAIT(1); }
        else               { CP_WAIT(0); }
        __syncthreads();

        const uint32_t bufA = sb + (it % 3) * STAGE_BYTES;
        const uint32_t bufB = bufA + A_BYTES;

        #pragma unroll
        for (int kk = 0; kk < 4; ++kk) {
            uint32_t ah[4][4], bh[2][4];
            #pragma unroll
            for (int mt = 0; mt < 4; ++mt) {
                uint32_t off = SWZ(((aRow + mt * 16) * 64 + kk * 16 + aK) * 2);
                ldsm_x4(ah[mt], bufA + off);
            }
            #pragma unroll
            for (int np = 0; np < 2; ++np) {
                uint32_t off = SWZ(((bRow + np * 16) * 64 + kk * 16 + bK) * 2);
                ldsm_x4(bh[np], bufB + off);
            }
            #pragma unroll
            for (int mt = 0; mt < 4; ++mt)
                #pragma unroll
                for (int nt = 0; nt < 4; ++nt) {
                    const int np = nt >> 1, q = (nt & 1) * 2;
                    mma16816(acc[mt][nt], ah[mt], bh[np][q], bh[np][q + 1]);
                }
        }
        __syncthreads();
        if (it + 3 < 16) load_stage(it % 3, (it + 3) * 64);
    }

    #pragma unroll
    for (int mt = 0; mt < 4; ++mt)
        #pragma unroll
        for (int nt = 0; nt < 4; ++nt) {
            int r = rowBase + wm + mt * 16 + (lane >> 2);
            int n = nBase + wn + nt * 8 + (lane & 3) * 2;
            float* a4 = acc[mt][nt];
            if (proj) {
                __half* oh = (z == 0) ? gQh : (z == 1) ? gKh : gVh;
                int h = n >> 6, k = n & 63, b = r & 1, s = r >> 1;
                size_t i0 = (((size_t)h * BB + b) * SQ + s) * 64 + k;
                size_t i1 = i0 + 4 * 64;   // row r+8 -> s+4
                *(uint32_t*)(oh + i0) = pack_f16(a4[0], a4[1]);
                *(uint32_t*)(oh + i1) = pack_f16(a4[2], a4[3]);
            } else {
                *(float2*)(Yout + (size_t)r * DM + n)       = make_float2(a4[0], a4[1]);
                *(float2*)(Yout + (size_t)(r + 8) * DM + n) = make_float2(a4[2], a4[3]);
            }
        }
}

// ---------------------------------------------------------------------------
// fp16 tensor-core causal flash attention (champion version, unchanged):
// maxless softmax, exp on MUFU, row-sums via MMA, mask inside loop.
// CTA: 128 threads, 64 queries; 3-stage KV ring; 3 CTAs/SM.
// ---------------------------------------------------------------------------
#define ATT_QBYTES 8192             /* Q fp16 tile                       */
#define ATT_STAGE  16384            /* K 8K | V 8K                       */
#define ATT_SMEM   (1024 + ATT_QBYTES + 3*ATT_STAGE)
#define ONES2 0x3C003C00u           /* half2(1,1) */

__global__ __launch_bounds__(128, 3) void attn_kernel()
{
    extern __shared__ char smem[];
    const uint32_t sb  = (smem_u32(smem) + 1023u) & ~1023u;
    const uint32_t skv = sb + ATT_QBYTES;
    const int tid  = threadIdx.x;
    const int wid  = tid >> 5, lane = tid & 31;
    const int qt   = (int)gridDim.x - 1 - (int)blockIdx.x;   // heavy first
    const int hb   = blockIdx.y;
    const int hh   = hb >> 1, bb = hb & 1;
    const int wm   = wid * 16;

    const __half* qp = gQh + (size_t)hb * SQ * 64;
    const __half* kp = gKh + (size_t)hb * SQ * 64;
    const __half* vp = gVh + (size_t)hb * SQ * 64;

    const int rL = lane & 15;            // ldmatrix row part
    const int cL = (lane >> 4) * 8;      // ldmatrix col part
    const int nk = qt + 1;

    auto loadKV = [&](int buf, int kt) {
        const uint32_t base = skv + buf * ATT_STAGE;
        #pragma unroll
        for (int t2 = 0; t2 < 4; ++t2) {
            int c = tid + t2 * 128;          // 512 chunks per tensor
            int r = c >> 3, cc = c & 7;
            uint32_t doff = SWZ(r * 128 + cc * 16);
            size_t go = (size_t)(kt * 64 + r) * 64 + cc * 8;
            cp_async16(base +        doff, kp + go);
            cp_async16(base + 8192 + doff, vp + go);
        }
        CP_COMMIT();
    };

    // ---- issue Q group + first two KV groups, then build Q fragments ----
    uint32_t qh[4][4];
    {
        #pragma unroll
        for (int t2 = 0; t2 < 4; ++t2) {
            int c = tid + t2 * 128;          // 512 chunks
            int r = c >> 3, cc = c & 7;
            uint32_t doff = SWZ(r * 128 + cc * 16);
            cp_async16(sb + doff, qp + (size_t)(qt * 64 + r) * 64 + cc * 8);
        }
        CP_COMMIT();
        loadKV(0, 0);
        if (nk > 1) { loadKV(1, 1); CP_WAIT(2); } else { CP_WAIT(1); }
        __syncthreads();
        #pragma unroll
        for (int kk = 0; kk < 4; ++kk) {
            uint32_t off = SWZ((wm + rL) * 128 + (kk * 16 + cL) * 2);
            ldsm_x4(qh[kk], sb + off);
        }
    }

    float o[8][4] = {};
    float rs[4] = {};                        // row-sum accumulator (via MMA)
    const int row0 = qt * 64 + wm + (lane >> 2);
    const int row1 = row0 + 8;

    for (int kt = 0; kt < nk; ++kt) {
        if (kt + 1 < nk) { CP_WAIT(1); } else { CP_WAIT(0); }
        __syncthreads();
        if (kt + 2 < nk) loadKV((kt + 2) % 3, kt + 2);

        const uint32_t stK = skv + (kt % 3) * ATT_STAGE;
        const uint32_t stV = stK + 8192;

        // ---- S = Q K^T (fp16, fp32 acc); scale pre-folded into WQ ----
        float s[8][4] = {};
        #pragma unroll
        for (int kk = 0; kk < 4; ++kk) {
            #pragma unroll
            for (int np = 0; np < 4; ++np) {
                uint32_t off = SWZ((np * 16 + rL) * 128 + (kk * 16 + cL) * 2);
                uint32_t kh4[4];
                ldsm_x4(kh4, stK + off);
                mma16816(s[2*np],   qh[kk], kh4[0], kh4[2]);
                mma16816(s[2*np+1], qh[kk], kh4[1], kh4[3]);
            }
        }

        // ---- causal mask on the diagonal tile only ----
        if (kt == qt) {
            #pragma unroll
            for (int j = 0; j < 8; ++j) {
                int colb = kt * 64 + j * 8 + (lane & 3) * 2;
                if (colb     > row0) s[j][0] = -1e4f;
                if (colb + 1 > row0) s[j][1] = -1e4f;
                if (colb     > row1) s[j][2] = -1e4f;
                if (colb + 1 > row1) s[j][3] = -1e4f;
            }
        }

        // ---- maxless softmax: exp2 on MUFU, pack P, row-sums via MMA ----
        uint32_t ph[4][4];
        #pragma unroll
        for (int kk = 0; kk < 4; ++kk) {
            #pragma unroll
            for (int q = 0; q < 4; ++q) {
                float a = ex2(s[2*kk + (q >> 1)][(q & 1) * 2]);
                float b = ex2(s[2*kk + (q >> 1)][(q & 1) * 2 + 1]);
                ph[kk][q] = pack_f16(a, b);
            }
            mma16816(rs, ph[kk], ONES2, ONES2);   // rs[0]=row0 sum, rs[2]=row1 sum
        }

        // ---- O += P V (fp16, fp32 acc) ----
        #pragma unroll
        for (int kk = 0; kk < 4; ++kk) {
            #pragma unroll
            for (int np = 0; np < 4; ++np) {
                uint32_t off = SWZ((kk * 16 + rL) * 128 + (np * 16 + cL) * 2);
                uint32_t vh4[4];
                ldsm_x4_t(vh4, stV + off);
                mma16816(o[2*np],   ph[kk], vh4[0], vh4[1]);
                mma16816(o[2*np+1], ph[kk], vh4[2], vh4[3]);
            }
        }
    }

    // ---- finalize, write fp16 O (per-row sums; no shfl needed) ----
    const float inv0 = 1.f / rs[0], inv1 = 1.f / rs[2];
    const size_t or0 = (size_t)(row0 * 2 + bb) * DM;
    const size_t or1 = (size_t)(row1 * 2 + bb) * DM;
    #pragma unroll
    for (int j = 0; j < 8; ++j) {
        int vc = hh * 64 + j * 8 + (lane & 3) * 2;
        *(uint32_t*)(gOh + or0 + vc) = pack_f16(o[j][0] * inv0, o[j][1] * inv0);
        *(uint32_t*)(gOh + or1 + vc) = pack_f16(o[j][2] * inv1, o[j][3] * inv1);
    }
}

// ---------------------------------------------------------------------------
extern "C" void kernel_launch(void* const* d_in, const int* in_sizes, int n_in,
                              void* d_out, int out_size)
{
    (void)in_sizes; (void)n_in; (void)out_size;
    const float* Q  = (const float*)d_in[0];
    const float* K  = (const float*)d_in[1];
    const float* V  = (const float*)d_in[2];
    const float* WQ = (const float*)d_in[3];
    const float* WK = (const float*)d_in[4];
    const float* WV = (const float*)d_in[5];
    const float* WO = (const float*)d_in[6];
    float* Y = (float*)d_out;

    static int smem_set = 0;
    if (!smem_set) {
        cudaFuncSetAttribute(gemm_kernel, cudaFuncAttributeMaxDynamicSharedMemorySize, GEMM_SMEM);
        cudaFuncSetAttribute(attn_kernel, cudaFuncAttributeMaxDynamicSharedMemorySize, ATT_SMEM);
        smem_set = 1;
    }

    prep_kernel<<<dim3(32, 32, 7), 256>>>(Q, K, V, WQ, WK, WV, WO);

    gemm_kernel<<<dim3(32, 16, 3), 128, GEMM_SMEM>>>(nullptr, 1);  // QKV proj

    attn_kernel<<<dim3(SQ/64, H*BB), 128, ATT_SMEM>>>();           // flash attention

    gemm_kernel<<<dim3(32, 16, 1), 128, GEMM_SMEM>>>(Y, 0);        // out proj
}